// round 1
// baseline (speedup 1.0000x reference)
#include <cuda_runtime.h>
#include <cstdint>

#define BATCH 8
#define SEQ   2048
#define DIM   128

// inverse temperature = 1/sqrt(128)
#define INV_TEMP 0.08838834764831843f

// scratch: 1/rowsum per (b, i)  (device global, no allocation)
__device__ float g_inv_rs[BATCH * SEQ];

// ---------------- packed f32x2 helpers ----------------
__device__ __forceinline__ void fma2(unsigned long long& acc,
                                     unsigned long long a,
                                     unsigned long long b) {
    asm("fma.rn.f32x2 %0, %1, %2, %0;" : "+l"(acc) : "l"(a), "l"(b));
}
__device__ __forceinline__ unsigned long long pack2(float x, float y) {
    unsigned long long r;
    asm("mov.b64 %0, {%1, %2};" : "=l"(r) : "f"(x), "f"(y));
    return r;
}
__device__ __forceinline__ float2 unpack2(unsigned long long v) {
    float2 f;
    asm("mov.b64 {%0, %1}, %2;" : "=f"(f.x), "=f"(f.y) : "l"(v));
    return f;
}

// =====================================================================
// Pass 1: u[b,i,j] = exp( (q[b,i,:] . v[b,j,:]) / sqrt(D) )   (unnormalized)
//         g_inv_rs[b,i] = 1 / sum_j u[b,i,j]
// CTA: 32 i-rows x full 2048 j (chunks of 64). 128 threads.
// smem: qs_t[128][34] (k-major q tile), vs_t[128][66] (k-major v chunk)
// =====================================================================
#define P1_QW 34
#define P1_VW 66
#define P1_SMEM ((DIM * P1_QW + DIM * P1_VW) * 4)

__global__ void __launch_bounds__(128)
pass1_kernel(const float* __restrict__ q, const float* __restrict__ v,
             float* __restrict__ u) {
    extern __shared__ float sm[];
    float* qs = sm;                 // [128][34]
    float* vs = sm + DIM * P1_QW;   // [128][66]

    const int b  = blockIdx.y;
    const int i0 = blockIdx.x * 32;
    const int t  = threadIdx.x;

    const float* qb = q + ((size_t)b * SEQ + i0) * DIM;
    const float* vb = v + (size_t)b * SEQ * DIM;
    float*       ub = u + ((size_t)b * SEQ + i0) * SEQ;

    // ---- load q tile transposed: qs[k][m] ----
#pragma unroll
    for (int it = 0; it < 8; ++it) {
        int idx = it * 128 + t;
        int m  = idx >> 5;     // 0..31
        int cg = idx & 31;     // float4 group along k
        float4 f = *(const float4*)(qb + (size_t)m * DIM + cg * 4);
        qs[(cg * 4 + 0) * P1_QW + m] = f.x;
        qs[(cg * 4 + 1) * P1_QW + m] = f.y;
        qs[(cg * 4 + 2) * P1_QW + m] = f.z;
        qs[(cg * 4 + 3) * P1_QW + m] = f.w;
    }

    const int tc = t & 7;      // j-group of 8
    const int tr = t >> 3;     // i-group of 2 (0..15)
    const int lane  = t & 31;
    const int cg_lo = lane & 7;
    const int n_lo  = lane >> 3;   // 0..3
    const int w     = t >> 5;      // warp id 0..3

    float rs0 = 0.0f, rs1 = 0.0f;

    for (int jc = 0; jc < SEQ / 64; ++jc) {
        __syncthreads();   // protect smem from previous iteration's readers

        // ---- load v chunk transposed: vs[k][n], rows j = jc*64+n ----
#pragma unroll
        for (int it = 0; it < 16; ++it) {
            int cg = cg_lo + 8 * (it & 3);               // 0..31
            int n  = n_lo + 4 * w + 16 * (it >> 2);      // 0..63
            float4 f = *(const float4*)(vb + (size_t)(jc * 64 + n) * DIM + cg * 4);
            vs[(cg * 4 + 0) * P1_VW + n] = f.x;
            vs[(cg * 4 + 1) * P1_VW + n] = f.y;
            vs[(cg * 4 + 2) * P1_VW + n] = f.z;
            vs[(cg * 4 + 3) * P1_VW + n] = f.w;
        }
        __syncthreads();

        // ---- 2(m) x 8(n) micro-tile GEMM, packed f32x2 ----
        unsigned long long acc[2][4];
#pragma unroll
        for (int mm = 0; mm < 2; ++mm)
#pragma unroll
            for (int p = 0; p < 4; ++p) acc[mm][p] = 0ull;

#pragma unroll 4
        for (int k = 0; k < DIM; ++k) {
            float2 a = *(const float2*)(qs + k * P1_QW + tr * 2);
            unsigned long long a0 = pack2(a.x, a.x);
            unsigned long long a1 = pack2(a.y, a.y);
            const unsigned long long* bp =
                (const unsigned long long*)(vs + k * P1_VW + tc * 8);
            unsigned long long b0 = bp[0], b1 = bp[1], b2 = bp[2], b3 = bp[3];
            fma2(acc[0][0], a0, b0); fma2(acc[0][1], a0, b1);
            fma2(acc[0][2], a0, b2); fma2(acc[0][3], a0, b3);
            fma2(acc[1][0], a1, b0); fma2(acc[1][1], a1, b1);
            fma2(acc[1][2], a1, b2); fma2(acc[1][3], a1, b3);
        }

        // ---- exp + store (coalesced float4) + rowsum accumulate ----
#pragma unroll
        for (int mm = 0; mm < 2; ++mm) {
            float e[8];
#pragma unroll
            for (int p = 0; p < 4; ++p) {
                float2 s = unpack2(acc[mm][p]);
                e[2 * p + 0] = __expf(s.x * INV_TEMP);
                e[2 * p + 1] = __expf(s.y * INV_TEMP);
            }
            float part = ((e[0] + e[1]) + (e[2] + e[3])) +
                         ((e[4] + e[5]) + (e[6] + e[7]));
            if (mm == 0) rs0 += part; else rs1 += part;

            float* r = ub + (size_t)(tr * 2 + mm) * SEQ + jc * 64 + tc * 8;
            *(float4*)(r)     = make_float4(e[0], e[1], e[2], e[3]);
            *(float4*)(r + 4) = make_float4(e[4], e[5], e[6], e[7]);
        }
    }

    // reduce rowsums over tc (xor within 8-lane groups)
#pragma unroll
    for (int o = 4; o >= 1; o >>= 1) {
        rs0 += __shfl_xor_sync(0xffffffffu, rs0, o);
        rs1 += __shfl_xor_sync(0xffffffffu, rs1, o);
    }
    if (tc == 0) {
        g_inv_rs[b * SEQ + i0 + tr * 2 + 0] = 1.0f / rs0;
        g_inv_rs[b * SEQ + i0 + tr * 2 + 1] = 1.0f / rs1;
    }
}

// =====================================================================
// Pass 2: attn[b,i,j] = u[b,i,j] * inv_rs[b,i]   (written back in place)
//         out[b,j,d]  = sum_i attn[b,i,j] * v[b,i,d]
// CTA: 32 j-columns x full d=128, streaming i in chunks of 64. 256 threads.
// =====================================================================
__global__ void __launch_bounds__(256)
pass2_kernel(const float* __restrict__ v, float* __restrict__ attn,
             float* __restrict__ out) {
    __shared__ float us[64][32];    // normalized attn chunk [i][j]
    __shared__ float vsS[64][128];  // v chunk [i][d]

    const int b  = blockIdx.y;
    const int j0 = blockIdx.x * 32;
    const int t  = threadIdx.x;
    const int tj = t & 15;    // j-group of 2
    const int td = t >> 4;    // d-group of 8 (0..15)

    const float* vb  = v + (size_t)b * SEQ * DIM;
    float*       ab  = attn + (size_t)b * SEQ * SEQ;
    const float* irs = g_inv_rs + b * SEQ;
    float*       ob  = out + (size_t)b * SEQ * DIM;

    unsigned long long acc[2][4];
#pragma unroll
    for (int jj = 0; jj < 2; ++jj)
#pragma unroll
        for (int p = 0; p < 4; ++p) acc[jj][p] = 0ull;

    for (int ic = 0; ic < SEQ / 64; ++ic) {
        const int i0 = ic * 64;
        __syncthreads();

        // ---- stage u chunk: normalize, write attn back, keep in smem ----
#pragma unroll
        for (int it = 0; it < 2; ++it) {
            int idx = it * 256 + t;
            int i  = idx >> 3;       // 0..63
            int jg = idx & 7;        // float4 group along j
            size_t ga = (size_t)(i0 + i) * SEQ + j0 + jg * 4;
            float4 f = *(const float4*)(ab + ga);
            float s = irs[i0 + i];
            f.x *= s; f.y *= s; f.z *= s; f.w *= s;
            *(float4*)(ab + ga) = f;              // final normalized attn
            *(float4*)(&us[i][jg * 4]) = f;
        }
        // ---- stage v chunk [64][128] ----
#pragma unroll
        for (int it = 0; it < 8; ++it) {
            int idx = it * 256 + t;
            int i  = idx >> 5;       // 0..63
            int cg = idx & 31;
            *(float4*)(&vsS[i][cg * 4]) =
                *(const float4*)(vb + (size_t)(i0 + i) * DIM + cg * 4);
        }
        __syncthreads();

        // ---- accumulate: 2(j) x 8(d) micro-tile ----
#pragma unroll 4
        for (int i = 0; i < 64; ++i) {
            float2 a = *(const float2*)(&us[i][tj * 2]);
            unsigned long long a0 = pack2(a.x, a.x);
            unsigned long long a1 = pack2(a.y, a.y);
            const unsigned long long* bp =
                (const unsigned long long*)(&vsS[i][td * 8]);
            unsigned long long b0 = bp[0], b1 = bp[1], b2 = bp[2], b3 = bp[3];
            fma2(acc[0][0], a0, b0); fma2(acc[0][1], a0, b1);
            fma2(acc[0][2], a0, b2); fma2(acc[0][3], a0, b3);
            fma2(acc[1][0], a1, b0); fma2(acc[1][1], a1, b1);
            fma2(acc[1][2], a1, b2); fma2(acc[1][3], a1, b3);
        }
    }

    // ---- write out tile ----
#pragma unroll
    for (int jj = 0; jj < 2; ++jj) {
        float2 o0 = unpack2(acc[jj][0]);
        float2 o1 = unpack2(acc[jj][1]);
        float2 o2 = unpack2(acc[jj][2]);
        float2 o3 = unpack2(acc[jj][3]);
        float* r = ob + (size_t)(j0 + tj * 2 + jj) * DIM + td * 8;
        *(float4*)(r)     = make_float4(o0.x, o0.y, o1.x, o1.y);
        *(float4*)(r + 4) = make_float4(o2.x, o2.y, o3.x, o3.y);
    }
}

// =====================================================================
extern "C" void kernel_launch(void* const* d_in, const int* in_sizes, int n_in,
                              void* d_out, int out_size) {
    const float* q = (const float*)d_in[0];
    // d_in[1] (k) is unused by the reference
    const float* v = (const float*)d_in[2];

    float* out  = (float*)d_out;                          // [8,2048,128]
    float* attn = out + (size_t)BATCH * SEQ * DIM;        // [8,2048,2048]

    cudaFuncSetAttribute(pass1_kernel,
                         cudaFuncAttributeMaxDynamicSharedMemorySize, P1_SMEM);

    dim3 g1(SEQ / 32, BATCH);
    pass1_kernel<<<g1, 128, P1_SMEM>>>(q, v, attn);

    dim3 g2(SEQ / 32, BATCH);
    pass2_kernel<<<g2, 256>>>(v, attn, out);
}

// round 2
// speedup vs baseline: 1.0418x; 1.0418x over previous
#include <cuda_runtime.h>
#include <cstdint>

#define BATCH 8
#define SEQ   2048
#define DIM   128

#define INV_TEMP 0.08838834764831843f

typedef unsigned long long ull;

// scratch: 1/rowsum per (b, i)
__device__ float g_inv_rs[BATCH * SEQ];

// ---------------- packed f32x2 helpers ----------------
__device__ __forceinline__ void fma2(ull& acc, ull a, ull b) {
    asm("fma.rn.f32x2 %0, %1, %2, %0;" : "+l"(acc) : "l"(a), "l"(b));
}
__device__ __forceinline__ ull pack2(float x, float y) {
    ull r;
    asm("mov.b64 %0, {%1, %2};" : "=l"(r) : "f"(x), "f"(y));
    return r;
}
__device__ __forceinline__ float2 unpack2(ull v) {
    float2 f;
    asm("mov.b64 {%0, %1}, %2;" : "=f"(f.x), "=f"(f.y) : "l"(v));
    return f;
}

// ---------------- cp.async helpers ----------------
__device__ __forceinline__ void cp_async16(void* smem_dst, const void* gmem_src) {
    unsigned a = (unsigned)__cvta_generic_to_shared(smem_dst);
    asm volatile("cp.async.ca.shared.global [%0], [%1], 16;\n"
                 :: "r"(a), "l"(gmem_src));
}
#define CP_COMMIT() asm volatile("cp.async.commit_group;\n" ::: "memory")
#define CP_WAIT0()  asm volatile("cp.async.wait_group 0;\n" ::: "memory")

// =====================================================================
// Pass 1: u[b,i,j] = exp( (q[b,i,:] . v[b,j,:]) / sqrt(D) )  (unnormalized)
//         g_inv_rs[b,i] = 1 / sum_j u[b,i,j]
// CTA: 64 i x 2048 j (chunks of 64), 256 threads, double-buffered v tiles
// with register-staged LDG -> STS transpose. One barrier per chunk.
// =====================================================================
#define P1_W 66
#define P1_SMEM ((size_t)3 * 128 * P1_W * 4)   // qs[128][66] + vs{0,1}[128][66]

__global__ void __launch_bounds__(256, 2)
pass1_kernel(const float* __restrict__ q, const float* __restrict__ v,
             float* __restrict__ u) {
    extern __shared__ float sm[];
    float* qs  = sm;                   // [128][P1_W] transposed q (k-major)
    float* vs0 = sm + 128 * P1_W;      // [128][P1_W] transposed v chunk
    float* vs1 = vs0 + 128 * P1_W;

    const int b  = blockIdx.y;
    const int i0 = blockIdx.x * 64;
    const int t  = threadIdx.x;
    const int lane  = t & 31;
    const int w     = t >> 5;
    const int cg_lo = lane & 7;      // float4 group along k (low part)
    const int r_lo  = lane >> 3;     // row (low part)

    const float* qb = q + ((size_t)b * SEQ + i0) * DIM;
    const float* vb = v + (size_t)b * SEQ * DIM;
    float*       ub = u + ((size_t)b * SEQ + i0) * SEQ;

    // ---- load q tile [64][128] transposed into qs[k][m] ----
#pragma unroll
    for (int it = 0; it < 8; ++it) {
        int cg = cg_lo + 8 * (it & 3);             // 0..31
        int m  = r_lo + 4 * w + 32 * (it >> 2);    // 0..63
        float4 f4 = *(const float4*)(qb + (size_t)m * DIM + cg * 4);
        qs[(cg * 4 + 0) * P1_W + m] = f4.x;
        qs[(cg * 4 + 1) * P1_W + m] = f4.y;
        qs[(cg * 4 + 2) * P1_W + m] = f4.z;
        qs[(cg * 4 + 3) * P1_W + m] = f4.w;
    }

    // ---- stage v chunk 0: LDG -> regs -> STS (transposed) ----
    float4 f[8];
#pragma unroll
    for (int it = 0; it < 8; ++it) {
        int cg = cg_lo + 8 * (it & 3);
        int n  = r_lo + 4 * w + 32 * (it >> 2);
        f[it] = *(const float4*)(vb + (size_t)n * DIM + cg * 4);
    }
#pragma unroll
    for (int it = 0; it < 8; ++it) {
        int cg = cg_lo + 8 * (it & 3);
        int n  = r_lo + 4 * w + 32 * (it >> 2);
        vs0[(cg * 4 + 0) * P1_W + n] = f[it].x;
        vs0[(cg * 4 + 1) * P1_W + n] = f[it].y;
        vs0[(cg * 4 + 2) * P1_W + n] = f[it].z;
        vs0[(cg * 4 + 3) * P1_W + n] = f[it].w;
    }
    // ---- prefetch chunk 1 into regs ----
#pragma unroll
    for (int it = 0; it < 8; ++it) {
        int cg = cg_lo + 8 * (it & 3);
        int n  = r_lo + 4 * w + 32 * (it >> 2);
        f[it] = *(const float4*)(vb + (size_t)(64 + n) * DIM + cg * 4);
    }
    __syncthreads();

    const int tc = t & 7;      // j-group of 8
    const int tr = t >> 3;     // i-group of 2 (0..31)
    float rs0 = 0.0f, rs1 = 0.0f;

    for (int jc = 0; jc < SEQ / 64; ++jc) {
        const float* vsb = (jc & 1) ? vs1 : vs0;

        ull acc[2][4];
#pragma unroll
        for (int mm = 0; mm < 2; ++mm)
#pragma unroll
            for (int p = 0; p < 4; ++p) acc[mm][p] = 0ull;

#pragma unroll 8
        for (int k = 0; k < DIM; ++k) {
            float2 a = *(const float2*)(qs + k * P1_W + tr * 2);
            ull a0 = pack2(a.x, a.x);
            ull a1 = pack2(a.y, a.y);
            const ull* bp = (const ull*)(vsb + k * P1_W + tc * 8);
            ull b0 = bp[0], b1 = bp[1], b2 = bp[2], b3 = bp[3];
            fma2(acc[0][0], a0, b0); fma2(acc[0][1], a0, b1);
            fma2(acc[0][2], a0, b2); fma2(acc[0][3], a0, b3);
            fma2(acc[1][0], a1, b0); fma2(acc[1][1], a1, b1);
            fma2(acc[1][2], a1, b2); fma2(acc[1][3], a1, b3);
        }

        // ---- epilogue: exp + rowsum + store ----
#pragma unroll
        for (int mm = 0; mm < 2; ++mm) {
            float e[8];
#pragma unroll
            for (int p = 0; p < 4; ++p) {
                float2 s = unpack2(acc[mm][p]);
                e[2 * p + 0] = __expf(s.x * INV_TEMP);
                e[2 * p + 1] = __expf(s.y * INV_TEMP);
            }
            float part = ((e[0] + e[1]) + (e[2] + e[3])) +
                         ((e[4] + e[5]) + (e[6] + e[7]));
            if (mm == 0) rs0 += part; else rs1 += part;

            float* r = ub + (size_t)(tr * 2 + mm) * SEQ + jc * 64 + tc * 8;
            *(float4*)(r)     = make_float4(e[0], e[1], e[2], e[3]);
            *(float4*)(r + 4) = make_float4(e[4], e[5], e[6], e[7]);
        }

        if (jc < SEQ / 64 - 1) {
            float* vsn = (jc & 1) ? vs0 : vs1;
            // STS staged chunk jc+1 (safe: its readers finished at sync jc-1)
#pragma unroll
            for (int it = 0; it < 8; ++it) {
                int cg = cg_lo + 8 * (it & 3);
                int n  = r_lo + 4 * w + 32 * (it >> 2);
                vsn[(cg * 4 + 0) * P1_W + n] = f[it].x;
                vsn[(cg * 4 + 1) * P1_W + n] = f[it].y;
                vsn[(cg * 4 + 2) * P1_W + n] = f[it].z;
                vsn[(cg * 4 + 3) * P1_W + n] = f[it].w;
            }
            if (jc < SEQ / 64 - 2) {
                const float* src = vb + (size_t)(jc + 2) * 64 * DIM;
#pragma unroll
                for (int it = 0; it < 8; ++it) {
                    int cg = cg_lo + 8 * (it & 3);
                    int n  = r_lo + 4 * w + 32 * (it >> 2);
                    f[it] = *(const float4*)(src + (size_t)n * DIM + cg * 4);
                }
            }
            __syncthreads();
        }
    }

    // rowsum reduce over tc (8 lanes) and write 1/rs
#pragma unroll
    for (int o = 4; o >= 1; o >>= 1) {
        rs0 += __shfl_xor_sync(0xffffffffu, rs0, o);
        rs1 += __shfl_xor_sync(0xffffffffu, rs1, o);
    }
    if (tc == 0) {
        g_inv_rs[b * SEQ + i0 + tr * 2 + 0] = 1.0f / rs0;
        g_inv_rs[b * SEQ + i0 + tr * 2 + 1] = 1.0f / rs1;
    }
}

// =====================================================================
// Pass 2: attn[b,i,j] = u[b,i,j] * inv_rs[b,i]   (written back in place)
//         out[b,j,d]  = sum_i attn[b,i,j] * v[b,i,d]
// CTA: 32 j x 128 d, 256 threads, i streamed in chunks of 32.
// v double-buffered via cp.async; u register-staged (RMW writeback).
// =====================================================================
#define P2_UW 36

__global__ void __launch_bounds__(256)
pass2_kernel(const float* __restrict__ v, float* __restrict__ attn,
             float* __restrict__ out) {
    __shared__ __align__(16) float us[32][P2_UW];     // normalized attn chunk
    __shared__ __align__(16) float vsm[2][32][128];   // v chunks (double buf)

    const int b  = blockIdx.y;
    const int j0 = blockIdx.x * 32;
    const int t  = threadIdx.x;
    const int tj = t & 15;    // j-group of 2
    const int td = t >> 4;    // d-group of 8
    const int ur = t >> 3;    // u row (0..31)
    const int ug = t & 7;     // u float4 group

    const float* vb  = v + (size_t)b * SEQ * DIM;
    float*       ab  = attn + (size_t)b * SEQ * SEQ;
    const float* irs = g_inv_rs + b * SEQ;
    float*       ob  = out + (size_t)b * SEQ * DIM;

    // ---- prologue: cp.async v chunk 0; LDG u chunk 0 + its inv_rs ----
#pragma unroll
    for (int it = 0; it < 4; ++it) {
        int idx = it * 256 + t;
        int i = idx >> 5, cg = idx & 31;
        cp_async16(&vsm[0][i][cg * 4], vb + (size_t)i * DIM + cg * 4);
    }
    CP_COMMIT();
    float4 ureg = *(const float4*)(ab + (size_t)ur * SEQ + j0 + ug * 4);
    float  sreg = __ldg(irs + ur);

    ull acc[2][4];
#pragma unroll
    for (int jj = 0; jj < 2; ++jj)
#pragma unroll
        for (int p = 0; p < 4; ++p) acc[jj][p] = 0ull;

    for (int ic = 0; ic < SEQ / 32; ++ic) {
        const int i0 = ic * 32;

        // normalize staged u, write final attn back to gmem
        float4 un = ureg;
        un.x *= sreg; un.y *= sreg; un.z *= sreg; un.w *= sreg;
        *(float4*)(ab + (size_t)(i0 + ur) * SEQ + j0 + ug * 4) = un;

        CP_WAIT0();            // v chunk ic landed
        __syncthreads();       // (A) everyone done with us + old v buffer

        *(float4*)(&us[ur][ug * 4]) = un;

        if (ic + 1 < SEQ / 32) {
            const float* vsrc = vb + (size_t)(i0 + 32) * DIM;
            float* vdst = &vsm[(ic + 1) & 1][0][0];
#pragma unroll
            for (int it = 0; it < 4; ++it) {
                int idx = it * 256 + t;
                int i = idx >> 5, cg = idx & 31;
                cp_async16(vdst + i * 128 + cg * 4,
                           vsrc + (size_t)i * DIM + cg * 4);
            }
            CP_COMMIT();
            ureg = *(const float4*)(ab + (size_t)(i0 + 32 + ur) * SEQ + j0 + ug * 4);
            sreg = __ldg(irs + i0 + 32 + ur);
        }
        __syncthreads();       // (B) us visible

        const float (*vsb)[128] = vsm[ic & 1];
#pragma unroll 8
        for (int i = 0; i < 32; ++i) {
            float2 a = *(const float2*)(&us[i][tj * 2]);
            ull a0 = pack2(a.x, a.x);
            ull a1 = pack2(a.y, a.y);
            const ull* bp = (const ull*)(&vsb[i][td * 8]);
            ull b0 = bp[0], b1 = bp[1], b2 = bp[2], b3 = bp[3];
            fma2(acc[0][0], a0, b0); fma2(acc[0][1], a0, b1);
            fma2(acc[0][2], a0, b2); fma2(acc[0][3], a0, b3);
            fma2(acc[1][0], a1, b0); fma2(acc[1][1], a1, b1);
            fma2(acc[1][2], a1, b2); fma2(acc[1][3], a1, b3);
        }
    }

    // ---- write out tile ----
#pragma unroll
    for (int jj = 0; jj < 2; ++jj) {
        float2 o0 = unpack2(acc[jj][0]);
        float2 o1 = unpack2(acc[jj][1]);
        float2 o2 = unpack2(acc[jj][2]);
        float2 o3 = unpack2(acc[jj][3]);
        float* r = ob + (size_t)(j0 + tj * 2 + jj) * DIM + td * 8;
        *(float4*)(r)     = make_float4(o0.x, o0.y, o1.x, o1.y);
        *(float4*)(r + 4) = make_float4(o2.x, o2.y, o3.x, o3.y);
    }
}

// =====================================================================
extern "C" void kernel_launch(void* const* d_in, const int* in_sizes, int n_in,
                              void* d_out, int out_size) {
    const float* q = (const float*)d_in[0];
    // d_in[1] (k) is unused by the reference
    const float* v = (const float*)d_in[2];

    float* out  = (float*)d_out;                      // [8,2048,128]
    float* attn = out + (size_t)BATCH * SEQ * DIM;    // [8,2048,2048]

    cudaFuncSetAttribute(pass1_kernel,
                         cudaFuncAttributeMaxDynamicSharedMemorySize,
                         (int)P1_SMEM);

    dim3 g1(SEQ / 64, BATCH);
    pass1_kernel<<<g1, 256, P1_SMEM>>>(q, v, attn);

    dim3 g2(SEQ / 32, BATCH);
    pass2_kernel<<<g2, 256>>>(v, attn, out);
}

// round 4
// speedup vs baseline: 2.5151x; 2.4143x over previous
#include <cuda_runtime.h>
#include <cuda_bf16.h>
#include <cstdint>

#define BATCH 8
#define SEQ   2048
#define DIM   128
#define INV_TEMP 0.08838834764831843f

typedef unsigned long long ull;

// ---------------- device scratch ----------------
__device__ float g_inv_rs[BATCH * SEQ];
__device__ __align__(16) __nv_bfloat16 g_qhi[BATCH * SEQ * DIM];
__device__ __align__(16) __nv_bfloat16 g_qlo[BATCH * SEQ * DIM];
__device__ __align__(16) __nv_bfloat16 g_vhi[BATCH * SEQ * DIM];
__device__ __align__(16) __nv_bfloat16 g_vlo[BATCH * SEQ * DIM];

// ---------------- cp.async ----------------
__device__ __forceinline__ void cp_async16(uint32_t smem_dst, const void* gsrc) {
    asm volatile("cp.async.ca.shared.global [%0], [%1], 16;\n"
                 :: "r"(smem_dst), "l"(gsrc));
}
#define CP_COMMIT() asm volatile("cp.async.commit_group;\n" ::: "memory")
#define CP_WAIT0()  asm volatile("cp.async.wait_group 0;\n" ::: "memory")
#define CP_WAIT1()  asm volatile("cp.async.wait_group 1;\n" ::: "memory")

__device__ __forceinline__ uint32_t smem_u32(const void* p) {
    uint32_t a;
    asm("{ .reg .u64 t; cvta.to.shared.u64 t, %1; cvt.u32.u64 %0, t; }"
        : "=r"(a) : "l"(p));
    return a;
}

// ---------------- mma / ldmatrix ----------------
__device__ __forceinline__ void ldm4(unsigned* r, uint32_t addr) {
    asm volatile("ldmatrix.sync.aligned.m8n8.x4.shared.b16 {%0,%1,%2,%3}, [%4];"
                 : "=r"(r[0]), "=r"(r[1]), "=r"(r[2]), "=r"(r[3]) : "r"(addr));
}
__device__ __forceinline__ void mma16816(float* d, const unsigned* a,
                                         const unsigned* b) {
    asm volatile(
        "mma.sync.aligned.m16n8k16.row.col.f32.bf16.bf16.f32 "
        "{%0,%1,%2,%3}, {%4,%5,%6,%7}, {%8,%9}, {%0,%1,%2,%3};"
        : "+f"(d[0]), "+f"(d[1]), "+f"(d[2]), "+f"(d[3])
        : "r"(a[0]), "r"(a[1]), "r"(a[2]), "r"(a[3]), "r"(b[0]), "r"(b[1]));
}

// =====================================================================
// split kernel: q,v -> bf16 hi/lo
// =====================================================================
__global__ void __launch_bounds__(256)
split_kernel(const float* __restrict__ q, const float* __restrict__ v) {
    int i = (blockIdx.x * 256 + threadIdx.x) * 4;
    float4 fq = *(const float4*)(q + i);
    float4 fv = *(const float4*)(v + i);
    float xq[4] = {fq.x, fq.y, fq.z, fq.w};
    float xv[4] = {fv.x, fv.y, fv.z, fv.w};
    __nv_bfloat16 qh[4], ql[4], vh[4], vl[4];
#pragma unroll
    for (int j = 0; j < 4; ++j) {
        qh[j] = __float2bfloat16(xq[j]);
        ql[j] = __float2bfloat16(xq[j] - __bfloat162float(qh[j]));
        vh[j] = __float2bfloat16(xv[j]);
        vl[j] = __float2bfloat16(xv[j] - __bfloat162float(vh[j]));
    }
    *(ull*)(g_qhi + i) = *(ull*)qh;
    *(ull*)(g_qlo + i) = *(ull*)ql;
    *(ull*)(g_vhi + i) = *(ull*)vh;
    *(ull*)(g_vlo + i) = *(ull*)vl;
}

// =====================================================================
// Pass 1 (mma.sync bf16 split): u = exp(q.v^T / sqrt(D)); inv rowsums.
// CTA: 128 i-rows, 256 thr (8 warps: 4m x 2n, warp tile 32x64).
// smem: Qlo tile (persistent) + double-buffered Vhi/Vlo tiles, pitch 272B.
// =====================================================================
#define PITCH 272                         // bytes per row (136 bf16)
#define TILE_B (128 * PITCH)              // 34816
#define OFF_QLO   0
#define OFF_VBUF(x) (TILE_B + (x) * (2 * TILE_B))   // vhi at +0, vlo at +TILE_B
#define OFF_RS    (TILE_B + 4 * TILE_B)             // 174080
#define P1_SMEM   (OFF_RS + 128 * 2 * 4)            // +1KB

// stage one 128x128 bf16 tile into padded smem
__device__ __forceinline__ void stage_tile(uint32_t dst,
                                           const __nv_bfloat16* src, int t) {
#pragma unroll
    for (int it = 0; it < 8; ++it) {
        int id = it * 256 + t;
        int r = id >> 4, c = id & 15;
        cp_async16(dst + r * PITCH + c * 16, src + r * 128 + c * 8);
    }
}

__global__ void __launch_bounds__(256, 1)
pass1_kernel(float* __restrict__ u) {
    extern __shared__ char sm[];
    const uint32_t smb = smem_u32(sm);
    float* rsbuf = (float*)(sm + OFF_RS);   // [128][2]

    const int b  = blockIdx.y;
    const int i0 = blockIdx.x * 128;
    const int t  = threadIdx.x;
    const int w  = t >> 5;
    const int l  = t & 31;
    const int wm = w & 3;        // warp m index (rows wm*32..+31)
    const int wn = w >> 2;       // warp n index (cols wn*64..+63)

    const __nv_bfloat16* qhg = g_qhi + ((size_t)b * SEQ + i0) * DIM;
    const __nv_bfloat16* qlg = g_qlo + ((size_t)b * SEQ + i0) * DIM;
    const __nv_bfloat16* vhg = g_vhi + (size_t)b * SEQ * DIM;
    const __nv_bfloat16* vlg = g_vlo + (size_t)b * SEQ * DIM;

    // lane offsets for ldmatrix address patterns
    const int rA = (l & 7) + ((l >> 3) & 1) * 8;   // A: row within 16
    const int cA = (l >> 4) * 8;                   // A: col offset
    const int rB = (l & 7) + (l >> 4) * 8;         // B: row within 16
    const int cB = ((l >> 3) & 1) * 8;             // B: col offset

    // ---- prologue: stage Qhi (into vbuf0) + Qlo (persistent) ----
    stage_tile(smb + OFF_VBUF(0), qhg, t);
    stage_tile(smb + OFF_QLO,     qlg, t);
    CP_COMMIT();
    CP_WAIT0();
    __syncthreads();

    // ---- load Qhi fragments to registers ----
    unsigned qh[2][8][4];
#pragma unroll
    for (int f = 0; f < 2; ++f)
#pragma unroll
        for (int k8 = 0; k8 < 8; ++k8) {
            uint32_t addr = smb + OFF_VBUF(0) +
                (wm * 32 + f * 16 + rA) * PITCH + (k8 * 16 + cA) * 2;
            ldm4(qh[f][k8], addr);
        }
    __syncthreads();   // done reading staging area

    // Qlo ldmatrix bases (per m-frag)
    uint32_t qloA[2];
#pragma unroll
    for (int f = 0; f < 2; ++f)
        qloA[f] = smb + OFF_QLO + (wm * 32 + f * 16 + rA) * PITCH + cA * 2;

    // B ldmatrix row offsets per n-frag-pair p
    uint32_t bRow[4];
#pragma unroll
    for (int p = 0; p < 4; ++p)
        bRow[p] = (wn * 64 + p * 16 + rB) * PITCH + cB * 2;

    // ---- prefetch V chunks 0,1 ----
    stage_tile(smb + OFF_VBUF(0),          vhg, t);
    stage_tile(smb + OFF_VBUF(0) + TILE_B, vlg, t);
    CP_COMMIT();
    stage_tile(smb + OFF_VBUF(1),          vhg + 128 * DIM, t);
    stage_tile(smb + OFF_VBUF(1) + TILE_B, vlg + 128 * DIM, t);
    CP_COMMIT();

    // per-thread u output pointers
    float* up[2];
#pragma unroll
    for (int f = 0; f < 2; ++f)
        up[f] = u + ((size_t)(b * SEQ + i0 + wm * 32 + f * 16 + (l >> 2))) * SEQ
                  + wn * 64 + (l & 3) * 2;

    float rs[2][2] = {{0.f, 0.f}, {0.f, 0.f}};
    const int NCHUNK = SEQ / 128;

    for (int c = 0; c < NCHUNK; ++c) {
        CP_WAIT1();
        __syncthreads();   // chunk c visible to all

        const uint32_t vh = smb + OFF_VBUF(c & 1);
        const uint32_t vl = vh + TILE_B;

        float acc[2][8][4];
#pragma unroll
        for (int f = 0; f < 2; ++f)
#pragma unroll
            for (int n = 0; n < 8; ++n)
#pragma unroll
                for (int x = 0; x < 4; ++x) acc[f][n][x] = 0.0f;

#pragma unroll
        for (int k8 = 0; k8 < 8; ++k8) {
            unsigned bh[4][4];
#pragma unroll
            for (int p = 0; p < 4; ++p)
                ldm4(bh[p], vh + bRow[p] + k8 * 32);
            unsigned al[2][4];
            ldm4(al[0], qloA[0] + k8 * 32);
            ldm4(al[1], qloA[1] + k8 * 32);
#pragma unroll
            for (int p = 0; p < 4; ++p)
#pragma unroll
                for (int h = 0; h < 2; ++h) {
                    const unsigned* bb = &bh[p][2 * h];
                    int n = 2 * p + h;
                    mma16816(acc[0][n], qh[0][k8], bb);   // Qhi . Vhi
                    mma16816(acc[1][n], qh[1][k8], bb);
                    mma16816(acc[0][n], al[0], bb);       // Qlo . Vhi
                    mma16816(acc[1][n], al[1], bb);
                }
            unsigned bl[4][4];
#pragma unroll
            for (int p = 0; p < 4; ++p)
                ldm4(bl[p], vl + bRow[p] + k8 * 32);
#pragma unroll
            for (int p = 0; p < 4; ++p)
#pragma unroll
                for (int h = 0; h < 2; ++h) {
                    const unsigned* bb = &bl[p][2 * h];
                    int n = 2 * p + h;
                    mma16816(acc[0][n], qh[0][k8], bb);   // Qhi . Vlo
                    mma16816(acc[1][n], qh[1][k8], bb);
                }
        }

        __syncthreads();   // all warps done reading buf (c&1)

        if (c + 2 < NCHUNK) {
            const uint32_t nb = smb + OFF_VBUF(c & 1);
            stage_tile(nb,          vhg + (size_t)(c + 2) * 128 * DIM, t);
            stage_tile(nb + TILE_B, vlg + (size_t)(c + 2) * 128 * DIM, t);
        }
        CP_COMMIT();   // keep group count in lockstep even on tail chunks

        // ---- epilogue: exp + rowsum + store (register-resident) ----
#pragma unroll
        for (int f = 0; f < 2; ++f) {
            float* row0 = up[f] + c * 128;
            float* row1 = row0 + 8 * SEQ;
#pragma unroll
            for (int n = 0; n < 8; ++n) {
                float e0 = __expf(acc[f][n][0] * INV_TEMP);
                float e1 = __expf(acc[f][n][1] * INV_TEMP);
                float e2 = __expf(acc[f][n][2] * INV_TEMP);
                float e3 = __expf(acc[f][n][3] * INV_TEMP);
                rs[f][0] += e0 + e1;
                rs[f][1] += e2 + e3;
                *(float2*)(row0 + n * 8) = make_float2(e0, e1);
                *(float2*)(row1 + n * 8) = make_float2(e2, e3);
            }
        }
    }

    // ---- rowsums: quad-reduce, cross-warp combine via smem ----
#pragma unroll
    for (int f = 0; f < 2; ++f)
#pragma unroll
        for (int h = 0; h < 2; ++h) {
            rs[f][h] += __shfl_xor_sync(0xffffffffu, rs[f][h], 1);
            rs[f][h] += __shfl_xor_sync(0xffffffffu, rs[f][h], 2);
        }
    if ((l & 3) == 0) {
#pragma unroll
        for (int f = 0; f < 2; ++f)
#pragma unroll
            for (int h = 0; h < 2; ++h) {
                int row = wm * 32 + f * 16 + h * 8 + (l >> 2);
                rsbuf[row * 2 + wn] = rs[f][h];
            }
    }
    __syncthreads();
    if (t < 128)
        g_inv_rs[b * SEQ + i0 + t] = 1.0f / (rsbuf[t * 2] + rsbuf[t * 2 + 1]);
}

// =====================================================================
// Pass 2 (SIMT fp32, unchanged): attn = u * inv_rs (in place); out = attn^T v
// =====================================================================
__device__ __forceinline__ void fma2(ull& acc, ull a, ull bb) {
    asm("fma.rn.f32x2 %0, %1, %2, %0;" : "+l"(acc) : "l"(a), "l"(bb));
}
__device__ __forceinline__ ull pack2(float x, float y) {
    ull r; asm("mov.b64 %0, {%1, %2};" : "=l"(r) : "f"(x), "f"(y)); return r;
}
__device__ __forceinline__ float2 unpack2(ull v) {
    float2 f; asm("mov.b64 {%0, %1}, %2;" : "=f"(f.x), "=f"(f.y) : "l"(v)); return f;
}
__device__ __forceinline__ void cp_async16g(void* smem_dst, const void* gmem_src) {
    unsigned a = (unsigned)__cvta_generic_to_shared(smem_dst);
    asm volatile("cp.async.ca.shared.global [%0], [%1], 16;\n" :: "r"(a), "l"(gmem_src));
}

#define P2_UW 36

__global__ void __launch_bounds__(256)
pass2_kernel(const float* __restrict__ v, float* __restrict__ attn,
             float* __restrict__ out) {
    __shared__ __align__(16) float us[32][P2_UW];
    __shared__ __align__(16) float vsm[2][32][128];

    const int b  = blockIdx.y;
    const int j0 = blockIdx.x * 32;
    const int t  = threadIdx.x;
    const int tj = t & 15;
    const int td = t >> 4;
    const int ur = t >> 3;
    const int ug = t & 7;

    const float* vb  = v + (size_t)b * SEQ * DIM;
    float*       ab  = attn + (size_t)b * SEQ * SEQ;
    const float* irs = g_inv_rs + b * SEQ;
    float*       ob  = out + (size_t)b * SEQ * DIM;

#pragma unroll
    for (int it = 0; it < 4; ++it) {
        int idx = it * 256 + t;
        int i = idx >> 5, cg = idx & 31;
        cp_async16g(&vsm[0][i][cg * 4], vb + (size_t)i * DIM + cg * 4);
    }
    CP_COMMIT();
    float4 ureg = *(const float4*)(ab + (size_t)ur * SEQ + j0 + ug * 4);
    float  sreg = __ldg(irs + ur);

    ull acc[2][4];
#pragma unroll
    for (int jj = 0; jj < 2; ++jj)
#pragma unroll
        for (int p = 0; p < 4; ++p) acc[jj][p] = 0ull;

    for (int ic = 0; ic < SEQ / 32; ++ic) {
        const int i0 = ic * 32;
        float4 un = ureg;
        un.x *= sreg; un.y *= sreg; un.z *= sreg; un.w *= sreg;
        *(float4*)(ab + (size_t)(i0 + ur) * SEQ + j0 + ug * 4) = un;

        CP_WAIT0();
        __syncthreads();
        *(float4*)(&us[ur][ug * 4]) = un;

        if (ic + 1 < SEQ / 32) {
            const float* vsrc = vb + (size_t)(i0 + 32) * DIM;
            float* vdst = &vsm[(ic + 1) & 1][0][0];
#pragma unroll
            for (int it = 0; it < 4; ++it) {
                int idx = it * 256 + t;
                int i = idx >> 5, cg = idx & 31;
                cp_async16g(vdst + i * 128 + cg * 4, vsrc + (size_t)i * DIM + cg * 4);
            }
            CP_COMMIT();
            ureg = *(const float4*)(ab + (size_t)(i0 + 32 + ur) * SEQ + j0 + ug * 4);
            sreg = __ldg(irs + i0 + 32 + ur);
        }
        __syncthreads();

        const float (*vsb)[128] = vsm[ic & 1];
#pragma unroll 8
        for (int i = 0; i < 32; ++i) {
            float2 a = *(const float2*)(&us[i][tj * 2]);
            ull a0 = pack2(a.x, a.x);
            ull a1 = pack2(a.y, a.y);
            const ull* bp = (const ull*)(&vsb[i][td * 8]);
            ull b0 = bp[0], b1 = bp[1], b2 = bp[2], b3 = bp[3];
            fma2(acc[0][0], a0, b0); fma2(acc[0][1], a0, b1);
            fma2(acc[0][2], a0, b2); fma2(acc[0][3], a0, b3);
            fma2(acc[1][0], a1, b0); fma2(acc[1][1], a1, b1);
            fma2(acc[1][2], a1, b2); fma2(acc[1][3], a1, b3);
        }
    }

#pragma unroll
    for (int jj = 0; jj < 2; ++jj) {
        float2 o0 = unpack2(acc[jj][0]);
        float2 o1 = unpack2(acc[jj][1]);
        float2 o2 = unpack2(acc[jj][2]);
        float2 o3 = unpack2(acc[jj][3]);
        float* r = ob + (size_t)(j0 + tj * 2 + jj) * DIM + td * 8;
        *(float4*)(r)     = make_float4(o0.x, o0.y, o1.x, o1.y);
        *(float4*)(r + 4) = make_float4(o2.x, o2.y, o3.x, o3.y);
    }
}

// =====================================================================
extern "C" void kernel_launch(void* const* d_in, const int* in_sizes, int n_in,
                              void* d_out, int out_size) {
    const float* q = (const float*)d_in[0];
    // d_in[1] (k) unused by the reference
    const float* v = (const float*)d_in[2];

    float* out  = (float*)d_out;                      // [8,2048,128]
    float* attn = out + (size_t)BATCH * SEQ * DIM;    // [8,2048,2048]

    cudaFuncSetAttribute(pass1_kernel,
                         cudaFuncAttributeMaxDynamicSharedMemorySize, P1_SMEM);

    split_kernel<<<(BATCH * SEQ * DIM) / (256 * 4), 256>>>(q, v);

    dim3 g1(SEQ / 128, BATCH);
    pass1_kernel<<<g1, 256, P1_SMEM>>>(attn);

    dim3 g2(SEQ / 32, BATCH);
    pass2_kernel<<<g2, 256>>>(v, attn, out);
}